// round 1
// baseline (speedup 1.0000x reference)
#include <cuda_runtime.h>

// ---------------------------------------------------------------------------
// Problem constants (from reference):
//   x: (4, 4096, 1024) fp32, W_qkv: (1024, 3072), W_o: (1024, 1024)
//   H=16 heads, DK=64, CHUNK=64, nC=64 chunks, EPS=1e-5
// ---------------------------------------------------------------------------
namespace cfg {
constexpr int Dm   = 1024;
constexpr int NH   = 16;
constexpr int DK   = 64;
constexpr int CH   = 64;     // chunk length
constexpr int B    = 4;
constexpr int L    = 4096;
constexpr int NC   = L / CH; // 64
constexpr int T    = B * L;  // 16384 tokens
constexpr int QC   = 3 * Dm; // 3072 qkv columns
}

// Scratch (static device globals — no runtime allocation allowed)
__device__ float g_qkv[(size_t)cfg::T * cfg::QC];                       // 192 MiB
__device__ float g_state[(size_t)cfg::B * cfg::NH * cfg::NC * cfg::DK * cfg::DK]; // 64 MiB
__device__ float g_y[(size_t)cfg::T * cfg::Dm];                         // 64 MiB

// ---------------------------------------------------------------------------
// Generic fp32 SGEMM: C[M,N] = A[M,K] @ B[K,N], row-major, dims % {128,128,8}==0
// 128x128 block tile, 8x8 per-thread micro-tile, 256 threads.
// ---------------------------------------------------------------------------
__global__ __launch_bounds__(256) void sgemm_kernel(
    const float* __restrict__ A, const float* __restrict__ B,
    float* __restrict__ C, int M, int N, int K)
{
    constexpr int BM = 128, BN = 128, BK = 8;
    __shared__ float As[BK][BM];   // transposed A tile
    __shared__ float Bs[BK][BN];

    const int tid  = threadIdx.x;
    const int tr   = (tid >> 4) << 3;    // 0..120, row base of 8x8 tile
    const int tc   = (tid & 15) << 3;    // 0..120, col base
    const int arow = tid >> 1;           // 0..127
    const int acol = (tid & 1) << 2;     // 0 or 4
    const int brow = tid >> 5;           // 0..7
    const int bcol = (tid & 31) << 2;    // 0..124

    const float* Ab = A + (size_t)blockIdx.y * BM * K;
    const float* Bb = B + (size_t)blockIdx.x * BN;

    float acc[8][8];
#pragma unroll
    for (int i = 0; i < 8; ++i)
#pragma unroll
        for (int j = 0; j < 8; ++j) acc[i][j] = 0.f;

    for (int k0 = 0; k0 < K; k0 += BK) {
        float4 av = *(const float4*)(Ab + (size_t)arow * K + k0 + acol);
        As[acol + 0][arow] = av.x;
        As[acol + 1][arow] = av.y;
        As[acol + 2][arow] = av.z;
        As[acol + 3][arow] = av.w;
        *(float4*)&Bs[brow][bcol] =
            *(const float4*)(Bb + (size_t)(k0 + brow) * N + bcol);
        __syncthreads();
#pragma unroll
        for (int kk = 0; kk < BK; ++kk) {
            float4 a0 = *(const float4*)&As[kk][tr];
            float4 a1 = *(const float4*)&As[kk][tr + 4];
            float4 b0 = *(const float4*)&Bs[kk][tc];
            float4 b1 = *(const float4*)&Bs[kk][tc + 4];
            float ar[8] = {a0.x, a0.y, a0.z, a0.w, a1.x, a1.y, a1.z, a1.w};
            float br[8] = {b0.x, b0.y, b0.z, b0.w, b1.x, b1.y, b1.z, b1.w};
#pragma unroll
            for (int i = 0; i < 8; ++i)
#pragma unroll
                for (int j = 0; j < 8; ++j)
                    acc[i][j] = fmaf(ar[i], br[j], acc[i][j]);
        }
        __syncthreads();
    }

    float* Cb = C + (size_t)(blockIdx.y * BM + tr) * N + blockIdx.x * BN + tc;
#pragma unroll
    for (int i = 0; i < 8; ++i) {
        *(float4*)(Cb + (size_t)i * N)     = make_float4(acc[i][0], acc[i][1], acc[i][2], acc[i][3]);
        *(float4*)(Cb + (size_t)i * N + 4) = make_float4(acc[i][4], acc[i][5], acc[i][6], acc[i][7]);
    }
}

// ---------------------------------------------------------------------------
// Per (token, head) LayerNorm (no affine) of k in-place in qkv.
// One warp per (token, head); lane handles elements {lane, lane+32}.
// ---------------------------------------------------------------------------
__global__ __launch_bounds__(256) void ln_k_kernel(float* __restrict__ qkv)
{
    using namespace cfg;
    const int gid  = blockIdx.x * blockDim.x + threadIdx.x;
    const int w    = gid >> 5;
    const int lane = gid & 31;
    const int tok  = w >> 4;   // / NH
    const int h    = w & 15;
    float* kp = qkv + (size_t)tok * QC + Dm + h * DK;
    float v0 = kp[lane], v1 = kp[lane + 32];
    float s = v0 + v1;
#pragma unroll
    for (int o = 16; o > 0; o >>= 1) s += __shfl_xor_sync(0xffffffffu, s, o);
    const float mu = s * (1.f / 64.f);
    const float d0 = v0 - mu, d1 = v1 - mu;
    float q = d0 * d0 + d1 * d1;
#pragma unroll
    for (int o = 16; o > 0; o >>= 1) q += __shfl_xor_sync(0xffffffffu, q, o);
    const float rstd = rsqrtf(q * (1.f / 64.f) + 1e-5f);
    kp[lane]      = d0 * rstd;
    kp[lane + 32] = d1 * rstd;
}

// ---------------------------------------------------------------------------
// Per-chunk KV outer product: G[b,h,c][d][e] = sum_t v[t,d] * k[t,e]
// One block per (b,h,c); 256 threads; 4x4 per-thread tile.
// ---------------------------------------------------------------------------
__global__ __launch_bounds__(256) void chunk_kv_kernel(
    const float* __restrict__ qkv, float* __restrict__ G)
{
    using namespace cfg;
    __shared__ float ks[CH][DK];
    __shared__ float vs[CH][DK];
    const int bid = blockIdx.x;
    const int c = bid & 63, h = (bid >> 6) & 15, b = bid >> 10;
    const int tid = threadIdx.x;
    const float* base = qkv + (size_t)(b * L + c * CH) * QC + h * DK;

    for (int i = tid; i < CH * DK / 4; i += 256) {
        const int t = i >> 4, e4 = (i & 15) << 2;
        *(float4*)&ks[t][e4] = *(const float4*)(base + (size_t)t * QC + Dm + e4);
        *(float4*)&vs[t][e4] = *(const float4*)(base + (size_t)t * QC + 2 * Dm + e4);
    }
    __syncthreads();

    const int dr = (tid >> 4) << 2;   // d base
    const int ec = (tid & 15) << 2;   // e base
    float acc[4][4];
#pragma unroll
    for (int i = 0; i < 4; ++i)
#pragma unroll
        for (int j = 0; j < 4; ++j) acc[i][j] = 0.f;

    for (int t = 0; t < CH; ++t) {
        float4 vv = *(const float4*)&vs[t][dr];
        float4 kk = *(const float4*)&ks[t][ec];
        float va[4] = {vv.x, vv.y, vv.z, vv.w};
        float ka[4] = {kk.x, kk.y, kk.z, kk.w};
#pragma unroll
        for (int i = 0; i < 4; ++i)
#pragma unroll
            for (int j = 0; j < 4; ++j)
                acc[i][j] = fmaf(va[i], ka[j], acc[i][j]);
    }

    float* Gp = G + (size_t)((b * NH + h) * NC + c) * DK * DK;
#pragma unroll
    for (int i = 0; i < 4; ++i)
        *(float4*)(Gp + (size_t)(dr + i) * DK + ec) =
            make_float4(acc[i][0], acc[i][1], acc[i][2], acc[i][3]);
}

// ---------------------------------------------------------------------------
// In-place exclusive prefix over chunks: S_c = sum_{c'<c} G_{c'} per (b,h).
// One block per (b,h); each thread carries 16 running sums in registers.
// ---------------------------------------------------------------------------
__global__ __launch_bounds__(256) void prefix_kernel(float* __restrict__ G)
{
    using namespace cfg;
    const int bh  = blockIdx.x;
    const int tid = threadIdx.x;
    float run[16];
#pragma unroll
    for (int i = 0; i < 16; ++i) run[i] = 0.f;
    float* base = G + (size_t)bh * NC * DK * DK;
    for (int c = 0; c < NC; ++c) {
        float* p = base + (size_t)c * DK * DK;
#pragma unroll
        for (int i = 0; i < 16; ++i) {
            const int idx = tid + 256 * i;
            const float g = p[idx];
            p[idx] = run[i];
            run[i] += g;
        }
    }
}

// ---------------------------------------------------------------------------
// Per-chunk output: y = q_c @ S_c^T + tril(q_c k_c^T) @ v_c
// One block per (b,h,c); 48 KiB smem (3 x 64x64 fp32 buffers, role-rotated):
//   buf0: q^T   -> v          buf1: k^T -> S^T        buf2: scores^T
// All inner-loop smem reads are float4 / broadcast (conflict-free).
// ---------------------------------------------------------------------------
__global__ __launch_bounds__(256) void attn_kernel(
    const float* __restrict__ qkv, const float* __restrict__ Sx,
    float* __restrict__ y)
{
    using namespace cfg;
    __shared__ float buf0[DK][CH];
    __shared__ float buf1[DK][CH];
    __shared__ float buf2[CH][CH];

    const int bid = blockIdx.x;
    const int c = bid & 63, h = (bid >> 6) & 15, b = bid >> 10;
    const int tid = threadIdx.x;
    const float* base = qkv + (size_t)(b * L + c * CH) * QC + h * DK;

    // Stage 1: load q^T, k^T
    for (int i = tid; i < CH * DK / 4; i += 256) {
        const int t = i >> 4, e4 = (i & 15) << 2;
        float4 qv = *(const float4*)(base + (size_t)t * QC + e4);
        float4 kv = *(const float4*)(base + (size_t)t * QC + Dm + e4);
        buf0[e4 + 0][t] = qv.x; buf0[e4 + 1][t] = qv.y;
        buf0[e4 + 2][t] = qv.z; buf0[e4 + 3][t] = qv.w;
        buf1[e4 + 0][t] = kv.x; buf1[e4 + 1][t] = kv.y;
        buf1[e4 + 2][t] = kv.z; buf1[e4 + 3][t] = kv.w;
    }
    __syncthreads();

    const int rt = (tid >> 4) << 2;   // t base (rows)
    const int dd = (tid & 15) << 2;   // s / d base (cols)

    // Stage 2: scores^T[s][t] = tril mask * sum_e q[t][e] k[s][e]
    {
        float sc[4][4];
#pragma unroll
        for (int i = 0; i < 4; ++i)
#pragma unroll
            for (int j = 0; j < 4; ++j) sc[i][j] = 0.f;
        for (int e = 0; e < DK; ++e) {
            float4 q4 = *(const float4*)&buf0[e][rt];
            float4 k4 = *(const float4*)&buf1[e][dd];
            float qa[4] = {q4.x, q4.y, q4.z, q4.w};
            float ka[4] = {k4.x, k4.y, k4.z, k4.w};
#pragma unroll
            for (int i = 0; i < 4; ++i)
#pragma unroll
                for (int j = 0; j < 4; ++j)
                    sc[i][j] = fmaf(qa[i], ka[j], sc[i][j]);
        }
#pragma unroll
        for (int i = 0; i < 4; ++i)
#pragma unroll
            for (int j = 0; j < 4; ++j)
                buf2[dd + j][rt + i] = (dd + j <= rt + i) ? sc[i][j] : 0.f;
    }
    __syncthreads();

    // Stage 3: load S^T (exclusive-prefix state) into buf1
    {
        const float* Sp = Sx + (size_t)((b * NH + h) * NC + c) * DK * DK;
        for (int i = tid; i < DK * DK / 4; i += 256) {
            const int d = i >> 4, e4 = (i & 15) << 2;
            float4 sv = *(const float4*)(Sp + (size_t)d * DK + e4);
            buf1[e4 + 0][d] = sv.x; buf1[e4 + 1][d] = sv.y;
            buf1[e4 + 2][d] = sv.z; buf1[e4 + 3][d] = sv.w;
        }
    }
    __syncthreads();

    // Stage 4: inter[t][d] = sum_e q[t][e] * S[d][e]
    float acc[4][4];
#pragma unroll
    for (int i = 0; i < 4; ++i)
#pragma unroll
        for (int j = 0; j < 4; ++j) acc[i][j] = 0.f;
    for (int e = 0; e < DK; ++e) {
        float4 q4 = *(const float4*)&buf0[e][rt];
        float4 s4 = *(const float4*)&buf1[e][dd];
        float qa[4] = {q4.x, q4.y, q4.z, q4.w};
        float sa[4] = {s4.x, s4.y, s4.z, s4.w};
#pragma unroll
        for (int i = 0; i < 4; ++i)
#pragma unroll
            for (int j = 0; j < 4; ++j)
                acc[i][j] = fmaf(qa[i], sa[j], acc[i][j]);
    }
    __syncthreads();

    // Stage 5: load v row-major into buf0
    for (int i = tid; i < CH * DK / 4; i += 256) {
        const int t = i >> 4, e4 = (i & 15) << 2;
        *(float4*)&buf0[t][e4] = *(const float4*)(base + (size_t)t * QC + 2 * Dm + e4);
    }
    __syncthreads();

    // Stage 6: intra[t][d] += sum_s scores[t][s] * v[s][d]
    for (int s = 0; s < CH; ++s) {
        float4 sc4 = *(const float4*)&buf2[s][rt];
        float4 vv4 = *(const float4*)&buf0[s][dd];
        float sa[4] = {sc4.x, sc4.y, sc4.z, sc4.w};
        float va[4] = {vv4.x, vv4.y, vv4.z, vv4.w};
#pragma unroll
        for (int i = 0; i < 4; ++i)
#pragma unroll
            for (int j = 0; j < 4; ++j)
                acc[i][j] = fmaf(sa[i], va[j], acc[i][j]);
    }

    // Stage 7: write y[token, h*DK + d]
    float* yp = y + (size_t)(b * L + c * CH) * Dm + h * DK;
#pragma unroll
    for (int i = 0; i < 4; ++i)
        *(float4*)(yp + (size_t)(rt + i) * Dm + dd) =
            make_float4(acc[i][0], acc[i][1], acc[i][2], acc[i][3]);
}

// ---------------------------------------------------------------------------
// Launcher: qkv GEMM -> LN(k) -> chunk KV -> prefix scan -> attn -> out GEMM
// ---------------------------------------------------------------------------
extern "C" void kernel_launch(void* const* d_in, const int* in_sizes, int n_in,
                              void* d_out, int out_size)
{
    using namespace cfg;
    (void)in_sizes; (void)n_in; (void)out_size;
    const float* x    = (const float*)d_in[0];
    const float* Wqkv = (const float*)d_in[1];
    const float* Wo   = (const float*)d_in[2];
    float* out = (float*)d_out;

    float *qkv_p, *st_p, *y_p;
    cudaGetSymbolAddress((void**)&qkv_p, g_qkv);
    cudaGetSymbolAddress((void**)&st_p,  g_state);
    cudaGetSymbolAddress((void**)&y_p,   g_y);

    // 1) qkv = x @ W_qkv   (16384 x 3072 x 1024)
    sgemm_kernel<<<dim3(QC / 128, T / 128), 256>>>(x, Wqkv, qkv_p, T, QC, Dm);
    // 2) LayerNorm(k) in place, per (token, head)
    ln_k_kernel<<<(T * NH) / 8, 256>>>(qkv_p);
    // 3) Per-chunk KV outer products G_c (fully parallel)
    chunk_kv_kernel<<<B * NH * NC, 256>>>(qkv_p, st_p);
    // 4) Exclusive prefix over chunks -> S_c (in place)
    prefix_kernel<<<B * NH, 256>>>(st_p);
    // 5) y_c = q_c S_c^T + tril(q_c k_c^T) v_c (fully parallel)
    attn_kernel<<<B * NH * NC, 256>>>(qkv_p, st_p, y_p);
    // 6) out = y @ W_o     (16384 x 1024 x 1024)
    sgemm_kernel<<<dim3(Dm / 128, T / 128), 256>>>(y_p, Wo, out, T, Dm, Dm);
}

// round 3
// speedup vs baseline: 2.2297x; 2.2297x over previous
#include <cuda_runtime.h>
#include <cuda_bf16.h>
#include <cstdint>

// ---------------------------------------------------------------------------
// Problem constants
// ---------------------------------------------------------------------------
namespace cfg {
constexpr int Dm   = 1024;
constexpr int NH   = 16;
constexpr int DK   = 64;
constexpr int CH   = 64;
constexpr int B    = 4;
constexpr int L    = 4096;
constexpr int NC   = L / CH;   // 64
constexpr int T    = B * L;    // 16384
constexpr int QC   = 3 * Dm;   // 3072
}

// ---------------------------------------------------------------------------
// Static device scratch
// ---------------------------------------------------------------------------
__device__ float          g_qkv[(size_t)cfg::T * cfg::QC];
__device__ float          g_state[(size_t)cfg::B * cfg::NH * cfg::NC * cfg::DK * cfg::DK];
__device__ float          g_y[(size_t)cfg::T * cfg::Dm];
__device__ __nv_bfloat16  g_ahi[(size_t)cfg::T * cfg::Dm];
__device__ __nv_bfloat16  g_alo[(size_t)cfg::T * cfg::Dm];
__device__ __nv_bfloat16  g_wqh[(size_t)cfg::QC * cfg::Dm];
__device__ __nv_bfloat16  g_wql[(size_t)cfg::QC * cfg::Dm];
__device__ __nv_bfloat16  g_woh[(size_t)cfg::Dm * cfg::Dm];
__device__ __nv_bfloat16  g_wol[(size_t)cfg::Dm * cfg::Dm];

// ---------------------------------------------------------------------------
// PTX helpers (sm_80-era: cp.async + ldmatrix + mma.sync — legal at sm_103)
// ---------------------------------------------------------------------------
__device__ __forceinline__ uint32_t smem_u32(const void* p) {
    uint32_t a;
    asm("{ .reg .u64 t; cvta.to.shared.u64 t, %1; cvt.u32.u64 %0, t; }"
        : "=r"(a) : "l"(p));
    return a;
}
#define CP16(dst, src) \
    asm volatile("cp.async.cg.shared.global [%0], [%1], 16;" :: "r"(dst), "l"(src))
#define CP_COMMIT() asm volatile("cp.async.commit_group;" ::: "memory")
#define CP_WAIT(n)  asm volatile("cp.async.wait_group %0;" :: "n"(n) : "memory")

__device__ __forceinline__ void ldsm4(uint32_t* r, uint32_t addr) {
    asm volatile("ldmatrix.sync.aligned.m8n8.x4.shared.b16 {%0,%1,%2,%3}, [%4];"
                 : "=r"(r[0]), "=r"(r[1]), "=r"(r[2]), "=r"(r[3]) : "r"(addr));
}
__device__ __forceinline__ void mma16816(float* c, const uint32_t* a, const uint32_t* b) {
    asm volatile(
        "mma.sync.aligned.m16n8k16.row.col.f32.bf16.bf16.f32 "
        "{%0,%1,%2,%3}, {%4,%5,%6,%7}, {%8,%9}, {%0,%1,%2,%3};"
        : "+f"(c[0]), "+f"(c[1]), "+f"(c[2]), "+f"(c[3])
        : "r"(a[0]), "r"(a[1]), "r"(a[2]), "r"(a[3]), "r"(b[0]), "r"(b[1]));
}

// ---------------------------------------------------------------------------
// bf16 3x-split GEMM via HMMA:
//   C[M,N](fp32) = Ah@Bh^T + Ah@Bl^T + Al@Bh^T
//   A*: [M,K] bf16 row-major. B*: [N,K] bf16 row-major (pre-transposed W).
//   CTA tile 128x128, K-chunk = 64 halves (128B rows), 3-stage cp.async.
//   smem rows are 128B with chunk swizzle c ^= (row & 7): conflict-free ldsm.
// ---------------------------------------------------------------------------
namespace gm {
constexpr int TILE_B  = 128 * 128;       // 16 KiB per operand tile
constexpr int STAGE_B = 4 * TILE_B;      // 64 KiB per stage (Ah, Al, Bh, Bl)
constexpr int NSTAGE  = 3;
constexpr int SMEM_SZ = NSTAGE * STAGE_B; // 192 KiB
}

__global__ __launch_bounds__(256) void gemm_mma_kernel(
    const __nv_bfloat16* __restrict__ Ah, const __nv_bfloat16* __restrict__ Al,
    const __nv_bfloat16* __restrict__ Bh, const __nv_bfloat16* __restrict__ Bl,
    float* __restrict__ C, int N, int K)
{
    extern __shared__ char smem[];
    const uint32_t sb = smem_u32(smem);
    const int tid = threadIdx.x, wid = tid >> 5, lane = tid & 31;
    const int tn = blockIdx.x, tm = blockIdx.y;
    const int wm = wid >> 2;   // 0..1 : 64-row slab
    const int wn = wid & 3;    // 0..3 : 32-col slab

    const __nv_bfloat16* srcs[4] = {
        Ah + (size_t)tm * 128 * K, Al + (size_t)tm * 128 * K,
        Bh + (size_t)tn * 128 * K, Bl + (size_t)tn * 128 * K };

    const int lrow = tid >> 1;          // 0..127
    const int lc0  = (tid & 1) * 4;     // 0 or 4 (16B chunk index base)

    auto load_stage = [&](int chunk, int stage) {
        const uint32_t st = sb + stage * gm::STAGE_B;
#pragma unroll
        for (int t4 = 0; t4 < 4; ++t4) {
            const __nv_bfloat16* p = srcs[t4] + (size_t)lrow * K + chunk * 64;
            const uint32_t dst = st + t4 * gm::TILE_B + lrow * 128;
#pragma unroll
            for (int cc = 0; cc < 4; ++cc) {
                const int c = lc0 + cc;
                CP16(dst + ((c ^ (lrow & 7)) * 16), p + c * 8);
            }
        }
    };

    float acc[4][4][4];
#pragma unroll
    for (int t = 0; t < 4; ++t)
#pragma unroll
        for (int j = 0; j < 4; ++j)
#pragma unroll
            for (int r = 0; r < 4; ++r) acc[t][j][r] = 0.f;

    const int NK = K >> 6;   // 64-half chunks
    load_stage(0, 0); CP_COMMIT();
    load_stage(1, 1); CP_COMMIT();

    for (int i = 0; i < NK; ++i) {
        CP_WAIT(1);
        __syncthreads();
        if (i + 2 < NK) { load_stage(i + 2, (i + 2) % 3); CP_COMMIT(); }

        const uint32_t st  = sb + (i % 3) * gm::STAGE_B;
        const uint32_t ahB = st;
        const uint32_t alB = st + gm::TILE_B;
        const uint32_t bhB = st + 2 * gm::TILE_B;
        const uint32_t blB = st + 3 * gm::TILE_B;

#pragma unroll
        for (int s = 0; s < 4; ++s) {          // k16 steps within chunk
            uint32_t ah[4][4], al[4][4];
#pragma unroll
            for (int t = 0; t < 4; ++t) {
                const int row = wm * 64 + t * 16 + (lane & 15);
                const int c   = s * 2 + (lane >> 4);
                const uint32_t off = row * 128 + ((c ^ (row & 7)) * 16);
                ldsm4(ah[t], ahB + off);
                ldsm4(al[t], alB + off);
            }
            uint32_t bh[4][2], bl[4][2];
#pragma unroll
            for (int p = 0; p < 2; ++p) {      // pairs of n8 tiles
                const int row = wn * 32 + p * 16 + ((lane & 16) >> 1) + (lane & 7);
                const int c   = s * 2 + ((lane >> 3) & 1);
                const uint32_t off = row * 128 + ((c ^ (row & 7)) * 16);
                uint32_t r[4];
                ldsm4(r, bhB + off);
                bh[2 * p][0] = r[0]; bh[2 * p][1] = r[1];
                bh[2 * p + 1][0] = r[2]; bh[2 * p + 1][1] = r[3];
                ldsm4(r, blB + off);
                bl[2 * p][0] = r[0]; bl[2 * p][1] = r[1];
                bl[2 * p + 1][0] = r[2]; bl[2 * p + 1][1] = r[3];
            }
#pragma unroll
            for (int t = 0; t < 4; ++t)
#pragma unroll
                for (int j = 0; j < 4; ++j) {
                    mma16816(acc[t][j], ah[t], bh[j]);
                    mma16816(acc[t][j], ah[t], bl[j]);
                    mma16816(acc[t][j], al[t], bh[j]);
                }
        }
        __syncthreads();
    }

    // epilogue: fp32 stores, thread mapping per mma.m16n8 layout
    const int qr = lane >> 2, qc = (lane & 3) * 2;
#pragma unroll
    for (int t = 0; t < 4; ++t) {
        const int r0 = tm * 128 + wm * 64 + t * 16 + qr;
#pragma unroll
        for (int j = 0; j < 4; ++j) {
            const int col = tn * 128 + wn * 32 + j * 8 + qc;
            *(float2*)(C + (size_t)r0 * N + col)       = make_float2(acc[t][j][0], acc[t][j][1]);
            *(float2*)(C + (size_t)(r0 + 8) * N + col) = make_float2(acc[t][j][2], acc[t][j][3]);
        }
    }
}

// ---------------------------------------------------------------------------
// fp32 -> bf16 hi/lo split
// ---------------------------------------------------------------------------
__global__ __launch_bounds__(256) void split_kernel(
    const float* __restrict__ in, __nv_bfloat16* __restrict__ hi,
    __nv_bfloat16* __restrict__ lo, int n4)
{
    const int i = blockIdx.x * 256 + threadIdx.x;
    if (i >= n4) return;
    const float4 v = *(const float4*)(in + (size_t)i * 4);
    float xs[4] = {v.x, v.y, v.z, v.w};
    __nv_bfloat16 h[4], l[4];
#pragma unroll
    for (int j = 0; j < 4; ++j) {
        h[j] = __float2bfloat16_rn(xs[j]);
        l[j] = __float2bfloat16_rn(xs[j] - __bfloat162float(h[j]));
    }
    *(__nv_bfloat162*)(hi + (size_t)i * 4)     = __nv_bfloat162(h[0], h[1]);
    *(__nv_bfloat162*)(hi + (size_t)i * 4 + 2) = __nv_bfloat162(h[2], h[3]);
    *(__nv_bfloat162*)(lo + (size_t)i * 4)     = __nv_bfloat162(l[0], l[1]);
    *(__nv_bfloat162*)(lo + (size_t)i * 4 + 2) = __nv_bfloat162(l[2], l[3]);
}

// ---------------------------------------------------------------------------
// fp32 [K][N] -> bf16 hi/lo [N][K] (transpose + split) for weights
// ---------------------------------------------------------------------------
__global__ __launch_bounds__(256) void split_t_kernel(
    const float* __restrict__ in, __nv_bfloat16* __restrict__ hi,
    __nv_bfloat16* __restrict__ lo, int K, int N)
{
    __shared__ float t[32][33];
    const int tx = threadIdx.x & 31, ty = threadIdx.x >> 5;
    const int n0 = blockIdx.x * 32, k0 = blockIdx.y * 32;
#pragma unroll
    for (int r = 0; r < 4; ++r)
        t[ty + 8 * r][tx] = in[(size_t)(k0 + ty + 8 * r) * N + n0 + tx];
    __syncthreads();
#pragma unroll
    for (int r = 0; r < 4; ++r) {
        const int n = n0 + ty + 8 * r, k = k0 + tx;
        const float x = t[tx][ty + 8 * r];
        const __nv_bfloat16 h = __float2bfloat16_rn(x);
        hi[(size_t)n * K + k] = h;
        lo[(size_t)n * K + k] = __float2bfloat16_rn(x - __bfloat162float(h));
    }
}

// ---------------------------------------------------------------------------
// Per (token, head) LayerNorm of k in-place
// ---------------------------------------------------------------------------
__global__ __launch_bounds__(256) void ln_k_kernel(float* __restrict__ qkv)
{
    using namespace cfg;
    const int gid  = blockIdx.x * blockDim.x + threadIdx.x;
    const int w = gid >> 5, lane = gid & 31;
    const int tok = w >> 4, h = w & 15;
    float* kp = qkv + (size_t)tok * QC + Dm + h * DK;
    float v0 = kp[lane], v1 = kp[lane + 32];
    float s = v0 + v1;
#pragma unroll
    for (int o = 16; o > 0; o >>= 1) s += __shfl_xor_sync(0xffffffffu, s, o);
    const float mu = s * (1.f / 64.f);
    const float d0 = v0 - mu, d1 = v1 - mu;
    float q = d0 * d0 + d1 * d1;
#pragma unroll
    for (int o = 16; o > 0; o >>= 1) q += __shfl_xor_sync(0xffffffffu, q, o);
    const float rstd = rsqrtf(q * (1.f / 64.f) + 1e-5f);
    kp[lane]      = d0 * rstd;
    kp[lane + 32] = d1 * rstd;
}

// ---------------------------------------------------------------------------
// Per-chunk KV outer product
// ---------------------------------------------------------------------------
__global__ __launch_bounds__(256) void chunk_kv_kernel(
    const float* __restrict__ qkv, float* __restrict__ G)
{
    using namespace cfg;
    __shared__ float ks[CH][DK];
    __shared__ float vs[CH][DK];
    const int bid = blockIdx.x;
    const int c = bid & 63, h = (bid >> 6) & 15, b = bid >> 10;
    const int tid = threadIdx.x;
    const float* base = qkv + (size_t)(b * L + c * CH) * QC + h * DK;

    for (int i = tid; i < CH * DK / 4; i += 256) {
        const int t = i >> 4, e4 = (i & 15) << 2;
        *(float4*)&ks[t][e4] = *(const float4*)(base + (size_t)t * QC + Dm + e4);
        *(float4*)&vs[t][e4] = *(const float4*)(base + (size_t)t * QC + 2 * Dm + e4);
    }
    __syncthreads();

    const int dr = (tid >> 4) << 2, ec = (tid & 15) << 2;
    float acc[4][4];
#pragma unroll
    for (int i = 0; i < 4; ++i)
#pragma unroll
        for (int j = 0; j < 4; ++j) acc[i][j] = 0.f;

    for (int t = 0; t < CH; ++t) {
        float4 vv = *(const float4*)&vs[t][dr];
        float4 kk = *(const float4*)&ks[t][ec];
        float va[4] = {vv.x, vv.y, vv.z, vv.w};
        float ka[4] = {kk.x, kk.y, kk.z, kk.w};
#pragma unroll
        for (int i = 0; i < 4; ++i)
#pragma unroll
            for (int j = 0; j < 4; ++j)
                acc[i][j] = fmaf(va[i], ka[j], acc[i][j]);
    }
    float* Gp = G + (size_t)((b * NH + h) * NC + c) * DK * DK;
#pragma unroll
    for (int i = 0; i < 4; ++i)
        *(float4*)(Gp + (size_t)(dr + i) * DK + ec) =
            make_float4(acc[i][0], acc[i][1], acc[i][2], acc[i][3]);
}

// ---------------------------------------------------------------------------
// Exclusive prefix over chunks — one thread per state element (parallel)
// ---------------------------------------------------------------------------
__global__ __launch_bounds__(256) void prefix_kernel(float* __restrict__ G)
{
    using namespace cfg;
    const int slice = blockIdx.x & 15, bh = blockIdx.x >> 4;
    const int idx = slice * 256 + threadIdx.x;
    float* base = G + (size_t)bh * NC * DK * DK + idx;
    float run = 0.f;
#pragma unroll 4
    for (int c = 0; c < NC; ++c) {
        const float g = base[(size_t)c * DK * DK];
        base[(size_t)c * DK * DK] = run;
        run += g;
    }
}

// ---------------------------------------------------------------------------
// Per-chunk output: y = q_c @ S_c^T + tril(q_c k_c^T) @ v_c
// ---------------------------------------------------------------------------
__global__ __launch_bounds__(256) void attn_kernel(
    const float* __restrict__ qkv, const float* __restrict__ Sx,
    float* __restrict__ y)
{
    using namespace cfg;
    __shared__ float buf0[DK][CH];
    __shared__ float buf1[DK][CH];
    __shared__ float buf2[CH][CH];

    const int bid = blockIdx.x;
    const int c = bid & 63, h = (bid >> 6) & 15, b = bid >> 10;
    const int tid = threadIdx.x;
    const float* base = qkv + (size_t)(b * L + c * CH) * QC + h * DK;

    for (int i = tid; i < CH * DK / 4; i += 256) {
        const int t = i >> 4, e4 = (i & 15) << 2;
        float4 qv = *(const float4*)(base + (size_t)t * QC + e4);
        float4 kv = *(const float4*)(base + (size_t)t * QC + Dm + e4);
        buf0[e4 + 0][t] = qv.x; buf0[e4 + 1][t] = qv.y;
        buf0[e4 + 2][t] = qv.z; buf0[e4 + 3][t] = qv.w;
        buf1[e4 + 0][t] = kv.x; buf1[e4 + 1][t] = kv.y;
        buf1[e4 + 2][t] = kv.z; buf1[e4 + 3][t] = kv.w;
    }
    __syncthreads();

    const int rt = (tid >> 4) << 2, dd = (tid & 15) << 2;

    {
        float sc[4][4];
#pragma unroll
        for (int i = 0; i < 4; ++i)
#pragma unroll
            for (int j = 0; j < 4; ++j) sc[i][j] = 0.f;
        for (int e = 0; e < DK; ++e) {
            float4 q4 = *(const float4*)&buf0[e][rt];
            float4 k4 = *(const float4*)&buf1[e][dd];
            float qa[4] = {q4.x, q4.y, q4.z, q4.w};
            float ka[4] = {k4.x, k4.y, k4.z, k4.w};
#pragma unroll
            for (int i = 0; i < 4; ++i)
#pragma unroll
                for (int j = 0; j < 4; ++j)
                    sc[i][j] = fmaf(qa[i], ka[j], sc[i][j]);
        }
#pragma unroll
        for (int i = 0; i < 4; ++i)
#pragma unroll
            for (int j = 0; j < 4; ++j)
                buf2[dd + j][rt + i] = (dd + j <= rt + i) ? sc[i][j] : 0.f;
    }
    __syncthreads();

    {
        const float* Sp = Sx + (size_t)((b * NH + h) * NC + c) * DK * DK;
        for (int i = tid; i < DK * DK / 4; i += 256) {
            const int d = i >> 4, e4 = (i & 15) << 2;
            float4 sv = *(const float4*)(Sp + (size_t)d * DK + e4);
            buf1[e4 + 0][d] = sv.x; buf1[e4 + 1][d] = sv.y;
            buf1[e4 + 2][d] = sv.z; buf1[e4 + 3][d] = sv.w;
        }
    }
    __syncthreads();

    float acc[4][4];
#pragma unroll
    for (int i = 0; i < 4; ++i)
#pragma unroll
        for (int j = 0; j < 4; ++j) acc[i][j] = 0.f;
    for (int e = 0; e < DK; ++e) {
        float4 q4 = *(const float4*)&buf0[e][rt];
        float4 s4 = *(const float4*)&buf1[e][dd];
        float qa[4] = {q4.x, q4.y, q4.z, q4.w};
        float sa[4] = {s4.x, s4.y, s4.z, s4.w};
#pragma unroll
        for (int i = 0; i < 4; ++i)
#pragma unroll
            for (int j = 0; j < 4; ++j)
                acc[i][j] = fmaf(qa[i], sa[j], acc[i][j]);
    }
    __syncthreads();

    for (int i = tid; i < CH * DK / 4; i += 256) {
        const int t = i >> 4, e4 = (i & 15) << 2;
        *(float4*)&buf0[t][e4] = *(const float4*)(base + (size_t)t * QC + 2 * Dm + e4);
    }
    __syncthreads();

    for (int s = 0; s < CH; ++s) {
        float4 sc4 = *(const float4*)&buf2[s][rt];
        float4 vv4 = *(const float4*)&buf0[s][dd];
        float sa[4] = {sc4.x, sc4.y, sc4.z, sc4.w};
        float va[4] = {vv4.x, vv4.y, vv4.z, vv4.w};
#pragma unroll
        for (int i = 0; i < 4; ++i)
#pragma unroll
            for (int j = 0; j < 4; ++j)
                acc[i][j] = fmaf(sa[i], va[j], acc[i][j]);
    }

    float* yp = y + (size_t)(b * L + c * CH) * Dm + h * DK;
#pragma unroll
    for (int i = 0; i < 4; ++i)
        *(float4*)(yp + (size_t)(rt + i) * Dm + dd) =
            make_float4(acc[i][0], acc[i][1], acc[i][2], acc[i][3]);
}

// ---------------------------------------------------------------------------
// Launcher
// ---------------------------------------------------------------------------
extern "C" void kernel_launch(void* const* d_in, const int* in_sizes, int n_in,
                              void* d_out, int out_size)
{
    using namespace cfg;
    (void)in_sizes; (void)n_in; (void)out_size;
    const float* x    = (const float*)d_in[0];
    const float* Wqkv = (const float*)d_in[1];
    const float* Wo   = (const float*)d_in[2];
    float* out = (float*)d_out;

    float *qkv_p, *st_p, *y_p;
    __nv_bfloat16 *ah, *al, *wqh, *wql, *woh, *wol;
    cudaGetSymbolAddress((void**)&qkv_p, g_qkv);
    cudaGetSymbolAddress((void**)&st_p,  g_state);
    cudaGetSymbolAddress((void**)&y_p,   g_y);
    cudaGetSymbolAddress((void**)&ah,  g_ahi);
    cudaGetSymbolAddress((void**)&al,  g_alo);
    cudaGetSymbolAddress((void**)&wqh, g_wqh);
    cudaGetSymbolAddress((void**)&wql, g_wql);
    cudaGetSymbolAddress((void**)&woh, g_woh);
    cudaGetSymbolAddress((void**)&wol, g_wol);

    static int smem_set = 0;
    if (!smem_set) {
        cudaFuncSetAttribute(gemm_mma_kernel,
                             cudaFuncAttributeMaxDynamicSharedMemorySize, gm::SMEM_SZ);
        smem_set = 1;
    }

    const int n4x = T * Dm / 4;
    // 1) bf16 hi/lo splits (weights transposed to [N][K])
    split_kernel<<<(n4x + 255) / 256, 256>>>(x, ah, al, n4x);
    split_t_kernel<<<dim3(QC / 32, Dm / 32), 256>>>(Wqkv, wqh, wql, Dm, QC);
    split_t_kernel<<<dim3(Dm / 32, Dm / 32), 256>>>(Wo, woh, wol, Dm, Dm);

    // 2) qkv = x @ W_qkv  (HMMA 3x split)
    gemm_mma_kernel<<<dim3(QC / 128, T / 128), 256, gm::SMEM_SZ>>>(
        ah, al, wqh, wql, qkv_p, QC, Dm);

    // 3) LN(k), chunk KV, prefix, per-chunk attention
    ln_k_kernel<<<(T * NH) / 8, 256>>>(qkv_p);
    chunk_kv_kernel<<<B * NH * NC, 256>>>(qkv_p, st_p);
    prefix_kernel<<<B * NH * 16, 256>>>(st_p);
    attn_kernel<<<B * NH * NC, 256>>>(qkv_p, st_p, y_p);

    // 4) out = y @ W_o  (HMMA 3x split)
    split_kernel<<<(n4x + 255) / 256, 256>>>(y_p, ah, al, n4x);
    gemm_mma_kernel<<<dim3(Dm / 128, T / 128), 256, gm::SMEM_SZ>>>(
        ah, al, woh, wol, out, Dm, Dm);
}